// round 5
// baseline (speedup 1.0000x reference)
#include <cuda_runtime.h>
#include <cuda_bf16.h>
#include <math.h>

// Problem constants (shape-specialized benchmark)
#define BB      2
#define SEQ     4096
#define HID     1024
#define NH      16
#define HD      64
#define WIN     64
#define NWIN    (SEQ / WIN)          // 64
#define MROWS   (BB * SEQ)           // 8192

// ---------------- scratch (device globals; no cudaMalloc allowed) ----------
__device__ float g_q[MROWS * HID];
__device__ float g_k[MROWS * HID];
__device__ float g_v[MROWS * HID];
__device__ float g_att[MROWS * HID];

// ---------------- GEMM: C[M,N] = A[M,K] * B[N,K]^T + bias[N] ---------------
#define BM 128
#define BN 128
#define BK 16

__global__ __launch_bounds__(256, 2)
void gemm_nt_bias(const float* __restrict__ A, const float* __restrict__ Bm,
                  const float* __restrict__ bias, float* __restrict__ C,
                  int M, int N, int K)
{
    __shared__ float sA[BK][BM + 4];
    __shared__ float sB[BK][BN + 4];

    const int tid = threadIdx.x;
    const int tx  = tid & 15;        // 0..15 -> column group
    const int ty  = tid >> 4;        // 0..15 -> row group
    const int rowBase = blockIdx.y * BM;
    const int colBase = blockIdx.x * BN;

    const int lr  = tid >> 2;        // 0..63 (row within half-tile for loads)
    const int lc4 = tid & 3;         // which float4 along K

    float acc[8][8];
#pragma unroll
    for (int i = 0; i < 8; i++)
#pragma unroll
        for (int j = 0; j < 8; j++) acc[i][j] = 0.0f;

    for (int k0 = 0; k0 < K; k0 += BK) {
        // load A tile [BM x BK] and B tile [BN x BK], transposed into smem
#pragma unroll
        for (int half = 0; half < 2; half++) {
            const int r = lr + half * 64;
            float4 av = *(const float4*)(A + (size_t)(rowBase + r) * K + k0 + lc4 * 4);
            sA[lc4 * 4 + 0][r] = av.x;
            sA[lc4 * 4 + 1][r] = av.y;
            sA[lc4 * 4 + 2][r] = av.z;
            sA[lc4 * 4 + 3][r] = av.w;
            float4 bv = *(const float4*)(Bm + (size_t)(colBase + r) * K + k0 + lc4 * 4);
            sB[lc4 * 4 + 0][r] = bv.x;
            sB[lc4 * 4 + 1][r] = bv.y;
            sB[lc4 * 4 + 2][r] = bv.z;
            sB[lc4 * 4 + 3][r] = bv.w;
        }
        __syncthreads();

#pragma unroll
        for (int kk = 0; kk < BK; kk++) {
            float4 a0 = *(const float4*)&sA[kk][ty * 8];
            float4 a1 = *(const float4*)&sA[kk][ty * 8 + 4];
            float4 b0 = *(const float4*)&sB[kk][tx * 8];
            float4 b1 = *(const float4*)&sB[kk][tx * 8 + 4];
            float a[8] = {a0.x, a0.y, a0.z, a0.w, a1.x, a1.y, a1.z, a1.w};
            float b[8] = {b0.x, b0.y, b0.z, b0.w, b1.x, b1.y, b1.z, b1.w};
#pragma unroll
            for (int i = 0; i < 8; i++)
#pragma unroll
                for (int j = 0; j < 8; j++)
                    acc[i][j] = fmaf(a[i], b[j], acc[i][j]);
        }
        __syncthreads();
    }

    // epilogue: + bias, float4 stores
    float bb0[8];
#pragma unroll
    for (int j = 0; j < 8; j++) bb0[j] = bias[colBase + tx * 8 + j];

#pragma unroll
    for (int i = 0; i < 8; i++) {
        float* cp = C + (size_t)(rowBase + ty * 8 + i) * N + colBase + tx * 8;
        float4 v0 = make_float4(acc[i][0] + bb0[0], acc[i][1] + bb0[1],
                                acc[i][2] + bb0[2], acc[i][3] + bb0[3]);
        float4 v1 = make_float4(acc[i][4] + bb0[4], acc[i][5] + bb0[5],
                                acc[i][6] + bb0[6], acc[i][7] + bb0[7]);
        *(float4*)(cp)     = v0;
        *(float4*)(cp + 4) = v1;
    }
}

// ---------------- Windowed attention -----------------------------------
// One block per (window n, batch b). Loops over 16 heads:
//   S = scale * Qw Kw^T ; P = softmax(S) ; O = P Vw ; mean += P/16
// Writes attended (same [b,s,h*64+d] layout as projections) and the
// block-diagonal attn map block.
#define LDW 65   // smem row stride (64 + 1 pad)

__global__ __launch_bounds__(256)
void attn_windows(const float* __restrict__ Q, const float* __restrict__ Kp,
                  const float* __restrict__ V, float* __restrict__ attended,
                  float* __restrict__ attn)
{
    extern __shared__ float sm[];
    float* sQ    = sm;
    float* sK    = sQ + WIN * LDW;
    float* sV    = sK + WIN * LDW;
    float* sS    = sV + WIN * LDW;
    float* sMean = sS + WIN * LDW;

    const int n   = blockIdx.x;
    const int b   = blockIdx.y;
    const int tid = threadIdx.x;
    const int tx  = tid & 15;
    const int ty  = tid >> 4;
    const float scale = 0.125f;   // 1/sqrt(64)

    for (int e = tid; e < WIN * WIN; e += 256)
        sMean[(e >> 6) * LDW + (e & 63)] = 0.0f;
    __syncthreads();

    const size_t rowbase = (size_t)b * SEQ + (size_t)n * WIN;

    for (int h = 0; h < NH; h++) {
        // load 64x64 q,k,v tiles for this head (coalesced rows of 64 floats)
        for (int e = tid; e < WIN * WIN; e += 256) {
            const int r = e >> 6, c = e & 63;
            const size_t g = (rowbase + r) * HID + h * HD + c;
            sQ[r * LDW + c] = Q[g];
            sK[r * LDW + c] = Kp[g];
            sV[r * LDW + c] = V[g];
        }
        __syncthreads();

        // scores: 4x4 register tile per thread
        {
            float acc[4][4] = {};
#pragma unroll 8
            for (int d = 0; d < HD; d++) {
                float a0[4], b0[4];
#pragma unroll
                for (int i = 0; i < 4; i++) a0[i] = sQ[(ty * 4 + i) * LDW + d];
#pragma unroll
                for (int j = 0; j < 4; j++) b0[j] = sK[(tx * 4 + j) * LDW + d];
#pragma unroll
                for (int i = 0; i < 4; i++)
#pragma unroll
                    for (int j = 0; j < 4; j++)
                        acc[i][j] = fmaf(a0[i], b0[j], acc[i][j]);
            }
#pragma unroll
            for (int i = 0; i < 4; i++)
#pragma unroll
                for (int j = 0; j < 4; j++)
                    sS[(ty * 4 + i) * LDW + tx * 4 + j] = acc[i][j] * scale;
        }
        __syncthreads();

        // row softmax (one thread per row; deterministic sequential sums)
        if (tid < WIN) {
            float* row = sS + tid * LDW;
            float m = row[0];
#pragma unroll 8
            for (int j = 1; j < WIN; j++) m = fmaxf(m, row[j]);
            float s = 0.0f;
#pragma unroll 8
            for (int j = 0; j < WIN; j++) { float e = expf(row[j] - m); row[j] = e; s += e; }
            const float inv = 1.0f / s;
#pragma unroll 8
            for (int j = 0; j < WIN; j++) row[j] *= inv;
        }
        __syncthreads();

        // accumulate head-mean of weights
        for (int e = tid; e < WIN * WIN; e += 256) {
            const int r = e >> 6, c = e & 63;
            sMean[r * LDW + c] += sS[r * LDW + c] * (1.0f / NH);
        }

        // O = P @ V, 4x4 register tile
        {
            float o[4][4] = {};
#pragma unroll 8
            for (int j = 0; j < WIN; j++) {
                float w0[4], v0[4];
#pragma unroll
                for (int i = 0; i < 4; i++)  w0[i]  = sS[(ty * 4 + i) * LDW + j];
#pragma unroll
                for (int jj = 0; jj < 4; jj++) v0[jj] = sV[j * LDW + tx * 4 + jj];
#pragma unroll
                for (int i = 0; i < 4; i++)
#pragma unroll
                    for (int jj = 0; jj < 4; jj++)
                        o[i][jj] = fmaf(w0[i], v0[jj], o[i][jj]);
            }
#pragma unroll
            for (int i = 0; i < 4; i++) {
                float* op = attended + (rowbase + ty * 4 + i) * HID + h * HD + tx * 4;
                *(float4*)op = make_float4(o[i][0], o[i][1], o[i][2], o[i][3]);
            }
        }
        __syncthreads();   // protect tiles before next head's loads
    }

    // write the block-diagonal attention block (rest was memset to 0)
    for (int e = tid; e < WIN * WIN; e += 256) {
        const int r = e >> 6, c = e & 63;
        attn[(size_t)b * SEQ * SEQ + (size_t)(n * WIN + r) * SEQ + (size_t)n * WIN + c] =
            sMean[r * LDW + c];
    }
}

// ---------------- launch ------------------------------------------------
extern "C" void kernel_launch(void* const* d_in, const int* in_sizes, int n_in,
                              void* d_out, int out_size)
{
    (void)in_sizes; (void)n_in; (void)out_size;
    const float* query = (const float*)d_in[0];
    const float* key_i = (const float*)d_in[1];
    const float* value = (const float*)d_in[2];
    const float* Wq = (const float*)d_in[3];
    const float* bq = (const float*)d_in[4];
    const float* Wk = (const float*)d_in[5];
    const float* bk = (const float*)d_in[6];
    const float* Wv = (const float*)d_in[7];
    const float* bv = (const float*)d_in[8];
    const float* Wo = (const float*)d_in[9];
    const float* bo = (const float*)d_in[10];

    float* out  = (float*)d_out;                              // [B,S,HID]
    float* attn = out + (size_t)BB * SEQ * HID;               // [B,S,S]

    float *qb, *kb, *vb, *ab;
    cudaGetSymbolAddress((void**)&qb, g_q);
    cudaGetSymbolAddress((void**)&kb, g_k);
    cudaGetSymbolAddress((void**)&vb, g_v);
    cudaGetSymbolAddress((void**)&ab, g_att);

    const dim3 gemmGrid(HID / BN, MROWS / BM);   // (8, 64)

    // projections
    gemm_nt_bias<<<gemmGrid, 256>>>(query, Wq, bq, qb, MROWS, HID, HID);
    gemm_nt_bias<<<gemmGrid, 256>>>(key_i, Wk, bk, kb, MROWS, HID, HID);
    gemm_nt_bias<<<gemmGrid, 256>>>(value, Wv, bv, vb, MROWS, HID, HID);

    // zero the attention map, then fill block-diagonal blocks
    cudaMemsetAsync(attn, 0, (size_t)BB * SEQ * SEQ * sizeof(float), 0);

    const int smemAttn = 5 * WIN * LDW * (int)sizeof(float);  // 83,200 B
    cudaFuncSetAttribute(attn_windows, cudaFuncAttributeMaxDynamicSharedMemorySize, smemAttn);
    attn_windows<<<dim3(NWIN, BB), 256, smemAttn>>>(qb, kb, vb, ab, attn);

    // output projection
    gemm_nt_bias<<<gemmGrid, 256>>>(ab, Wo, bo, out, MROWS, HID, HID);
}

// round 6
// speedup vs baseline: 2.0147x; 2.0147x over previous
#include <cuda_runtime.h>
#include <cuda_bf16.h>
#include <math.h>

// Problem constants (shape-specialized benchmark)
#define BB      2
#define SEQ     4096
#define HID     1024
#define NH      16
#define HD      64
#define WIN     64
#define NWIN    (SEQ / WIN)          // 64
#define MROWS   (BB * SEQ)           // 8192
#define NGRP    4                    // head groups for attention
#define HPG     (NH / NGRP)          // heads per group

// ---------------- scratch (device globals; no cudaMalloc allowed) ----------
__device__ float g_q[MROWS * HID];
__device__ float g_k[MROWS * HID];
__device__ float g_v[MROWS * HID];
__device__ float g_att[MROWS * HID];
__device__ float g_pmean[(size_t)BB * NWIN * NGRP * WIN * WIN];   // 8 MB
__device__ __nv_bfloat16 g_ah[MROWS * HID];   // activation hi
__device__ __nv_bfloat16 g_al[MROWS * HID];   // activation lo
__device__ __nv_bfloat16 g_wh[HID * HID];     // weight hi
__device__ __nv_bfloat16 g_wl[HID * HID];     // weight lo

// ---------------- f32 -> bf16 hi/lo conversion -----------------------------
__global__ __launch_bounds__(256)
void conv_hilo(const float4* __restrict__ x, __nv_bfloat16* __restrict__ hi,
               __nv_bfloat16* __restrict__ lo, int n4)
{
    int i = blockIdx.x * blockDim.x + threadIdx.x;
    if (i >= n4) return;
    float4 v = x[i];
    float f[4] = {v.x, v.y, v.z, v.w};
    union { __nv_bfloat16 b[4]; uint2 u; } H, L;
#pragma unroll
    for (int j = 0; j < 4; j++) {
        H.b[j] = __float2bfloat16_rn(f[j]);
        L.b[j] = __float2bfloat16_rn(f[j] - __bfloat162float(H.b[j]));
    }
    *reinterpret_cast<uint2*>(hi + (size_t)i * 4) = H.u;
    *reinterpret_cast<uint2*>(lo + (size_t)i * 4) = L.u;
}

// ---------------- Tensor-core GEMM: C = A * B^T + bias ---------------------
// A[M,K], B[N,K] given as bf16 hi/lo pairs. Split product:
//   C ≈ Ah*Bh + Ah*Bl + Al*Bh  (fp32 accumulate)
// CTA tile 128x128x32, 8 warps of 64x32, mma.m16n8k16, cp.async 2-stage.

#define GBM 128
#define GBN 128
#define GBK 32
#define LDSW 20                        // smem words per row (16 data + 4 pad)
#define STG_W (128 * LDSW)             // words per array per stage (2560)

#define CP16(dst_u32, src_ptr) \
    asm volatile("cp.async.cg.shared.global [%0], [%1], 16;\n" :: "r"(dst_u32), "l"(src_ptr))
#define CP_COMMIT() asm volatile("cp.async.commit_group;\n" ::)
#define CP_WAIT(N)  asm volatile("cp.async.wait_group %0;\n" :: "n"(N))

#define LDSM4(R, ADDR) \
    asm volatile("ldmatrix.sync.aligned.m8n8.x4.shared.b16 {%0,%1,%2,%3}, [%4];" \
                 : "=r"((R)[0]), "=r"((R)[1]), "=r"((R)[2]), "=r"((R)[3]) : "r"(ADDR))

#define MMA16816(C, A, B0, B1) \
    asm volatile("mma.sync.aligned.m16n8k16.row.col.f32.bf16.bf16.f32 " \
                 "{%0,%1,%2,%3},{%4,%5,%6,%7},{%8,%9},{%0,%1,%2,%3};" \
                 : "+f"((C)[0]), "+f"((C)[1]), "+f"((C)[2]), "+f"((C)[3]) \
                 : "r"((A)[0]), "r"((A)[1]), "r"((A)[2]), "r"((A)[3]), "r"(B0), "r"(B1))

__global__ __launch_bounds__(256, 1)
void gemm_bf16split(const __nv_bfloat16* __restrict__ Ah, const __nv_bfloat16* __restrict__ Al,
                    const __nv_bfloat16* __restrict__ Bh, const __nv_bfloat16* __restrict__ Bl,
                    const float* __restrict__ bias, float* __restrict__ C,
                    int M, int N, int K)
{
    extern __shared__ unsigned int smem[];
    // layout (words): Ah[2][STG_W], Al[2][STG_W], Bh[2][STG_W], Bl[2][STG_W]
    const unsigned int sbase = (unsigned int)__cvta_generic_to_shared(smem);

    const int tid  = threadIdx.x;
    const int lane = tid & 31;
    const int warp = tid >> 5;
    const int wm   = warp & 1;          // 0..1 -> 64-row slab
    const int wn   = warp >> 1;         // 0..3 -> 32-col slab
    const int rowBase = blockIdx.y * GBM;
    const int colBase = blockIdx.x * GBN;
    const int NK = K / GBK;

    // ldmatrix per-lane offsets (bytes within one stage of one array)
    const int aRow = wm * 64 + ((lane >> 3) & 1) * 8 + (lane & 7);
    const unsigned int aOff = (unsigned int)(aRow * LDSW + (lane >> 4) * 4) * 4;
    const int bRow = wn * 32 + (lane >> 4) * 8 + (lane & 7);
    const unsigned int bOff = (unsigned int)(bRow * LDSW + ((lane >> 3) & 1) * 4) * 4;

    float acc[4][4][4];
#pragma unroll
    for (int i = 0; i < 4; i++)
#pragma unroll
        for (int j = 0; j < 4; j++)
#pragma unroll
            for (int r = 0; r < 4; r++) acc[i][j][r] = 0.0f;

    // ---- stage loader: 8 cp.async(16B) per thread ----
    auto load_stage = [&](int stage, int k0) {
#pragma unroll
        for (int it = 0; it < 2; it++) {
            const int cid = tid + it * 256;
            const int r = cid >> 2, c = cid & 3;
            const unsigned int soff = (unsigned int)(stage * STG_W + r * LDSW + c * 4) * 4;
            const size_t ga = (size_t)(rowBase + r) * K + k0 + c * 8;
            const size_t gb = (size_t)(colBase + r) * K + k0 + c * 8;
            CP16(sbase + 0 * STG_W * 8 + soff, Ah + ga);
            CP16(sbase + 2 * STG_W * 4 + soff, Al + ga);
            CP16(sbase + 4 * STG_W * 4 + soff, Bh + gb);
            CP16(sbase + 6 * STG_W * 4 + soff, Bl + gb);
        }
    };

    load_stage(0, 0);
    CP_COMMIT();

    for (int ks = 0; ks < NK; ks++) {
        if (ks + 1 < NK) {
            load_stage((ks + 1) & 1, (ks + 1) * GBK);
            CP_COMMIT();
            CP_WAIT(1);
        } else {
            CP_WAIT(0);
        }
        __syncthreads();

        const unsigned int st = (unsigned int)((ks & 1) * STG_W) * 4;
        const unsigned int baseAh = sbase + st;
        const unsigned int baseAl = sbase + 2 * STG_W * 4 + st;
        const unsigned int baseBh = sbase + 4 * STG_W * 4 + st;
        const unsigned int baseBl = sbase + 6 * STG_W * 4 + st;

#pragma unroll
        for (int half = 0; half < 2; half++) {
            const unsigned int kofs = (unsigned int)(half * 8) * 4;   // bytes
            unsigned int ah[4][4], al[4][4];
            unsigned int bh[4][2], bl[4][2];
#pragma unroll
            for (int mi = 0; mi < 4; mi++) {
                const unsigned int mo = (unsigned int)(mi * 16 * LDSW) * 4;
                LDSM4(ah[mi], baseAh + aOff + mo + kofs);
                LDSM4(al[mi], baseAl + aOff + mo + kofs);
            }
#pragma unroll
            for (int p = 0; p < 2; p++) {
                const unsigned int po = (unsigned int)(p * 16 * LDSW) * 4;
                unsigned int t[4];
                LDSM4(t, baseBh + bOff + po + kofs);
                bh[2 * p][0] = t[0]; bh[2 * p][1] = t[1];
                bh[2 * p + 1][0] = t[2]; bh[2 * p + 1][1] = t[3];
                LDSM4(t, baseBl + bOff + po + kofs);
                bl[2 * p][0] = t[0]; bl[2 * p][1] = t[1];
                bl[2 * p + 1][0] = t[2]; bl[2 * p + 1][1] = t[3];
            }
#pragma unroll
            for (int mi = 0; mi < 4; mi++)
#pragma unroll
                for (int ni = 0; ni < 4; ni++) {
                    MMA16816(acc[mi][ni], ah[mi], bh[ni][0], bh[ni][1]);
                    MMA16816(acc[mi][ni], ah[mi], bl[ni][0], bl[ni][1]);
                    MMA16816(acc[mi][ni], al[mi], bh[ni][0], bh[ni][1]);
                }
        }
        __syncthreads();
    }

    // ---- epilogue: + bias, float2 stores ----
    const int g  = lane >> 2;
    const int kp = lane & 3;
#pragma unroll
    for (int mi = 0; mi < 4; mi++) {
#pragma unroll
        for (int ni = 0; ni < 4; ni++) {
            const int col  = colBase + wn * 32 + ni * 8 + kp * 2;
            const int row0 = rowBase + wm * 64 + mi * 16 + g;
            const float2 bv = *reinterpret_cast<const float2*>(bias + col);
            float2 v0 = make_float2(acc[mi][ni][0] + bv.x, acc[mi][ni][1] + bv.y);
            float2 v1 = make_float2(acc[mi][ni][2] + bv.x, acc[mi][ni][3] + bv.y);
            *reinterpret_cast<float2*>(C + (size_t)row0 * N + col)       = v0;
            *reinterpret_cast<float2*>(C + (size_t)(row0 + 8) * N + col) = v1;
        }
    }
}

// ---------------- Windowed attention (head-group split) --------------------
#define LDW 65   // smem row stride (64 + 1 pad)

__global__ __launch_bounds__(256)
void attn_windows_g(const float* __restrict__ Q, const float* __restrict__ Kp,
                    const float* __restrict__ V, float* __restrict__ attended,
                    float* __restrict__ pmean)
{
    extern __shared__ float sm[];
    float* sQ    = sm;
    float* sK    = sQ + WIN * LDW;
    float* sV    = sK + WIN * LDW;
    float* sS    = sV + WIN * LDW;
    float* sMean = sS + WIN * LDW;

    const int n   = blockIdx.x;
    const int b   = blockIdx.y;
    const int grp = blockIdx.z;
    const int tid = threadIdx.x;
    const int tx  = tid & 15;
    const int ty  = tid >> 4;
    const float scale = 0.125f;   // 1/sqrt(64)

    for (int e = tid; e < WIN * WIN; e += 256)
        sMean[(e >> 6) * LDW + (e & 63)] = 0.0f;
    __syncthreads();

    const size_t rowbase = (size_t)b * SEQ + (size_t)n * WIN;

    for (int h = grp * HPG; h < grp * HPG + HPG; h++) {
        for (int e = tid; e < WIN * WIN; e += 256) {
            const int r = e >> 6, c = e & 63;
            const size_t gidx = (rowbase + r) * HID + h * HD + c;
            sQ[r * LDW + c] = Q[gidx];
            sK[r * LDW + c] = Kp[gidx];
            sV[r * LDW + c] = V[gidx];
        }
        __syncthreads();

        {   // scores: 4x4 register tile per thread
            float acc[4][4] = {};
#pragma unroll 8
            for (int d = 0; d < HD; d++) {
                float a0[4], b0[4];
#pragma unroll
                for (int i = 0; i < 4; i++) a0[i] = sQ[(ty * 4 + i) * LDW + d];
#pragma unroll
                for (int j = 0; j < 4; j++) b0[j] = sK[(tx * 4 + j) * LDW + d];
#pragma unroll
                for (int i = 0; i < 4; i++)
#pragma unroll
                    for (int j = 0; j < 4; j++)
                        acc[i][j] = fmaf(a0[i], b0[j], acc[i][j]);
            }
#pragma unroll
            for (int i = 0; i < 4; i++)
#pragma unroll
                for (int j = 0; j < 4; j++)
                    sS[(ty * 4 + i) * LDW + tx * 4 + j] = acc[i][j] * scale;
        }
        __syncthreads();

        // row softmax (one thread per row; deterministic)
        if (tid < WIN) {
            float* row = sS + tid * LDW;
            float m = row[0];
#pragma unroll 8
            for (int j = 1; j < WIN; j++) m = fmaxf(m, row[j]);
            float s = 0.0f;
#pragma unroll 8
            for (int j = 0; j < WIN; j++) { float e = expf(row[j] - m); row[j] = e; s += e; }
            const float inv = 1.0f / s;
#pragma unroll 8
            for (int j = 0; j < WIN; j++) row[j] *= inv;
        }
        __syncthreads();

        for (int e = tid; e < WIN * WIN; e += 256) {
            const int r = e >> 6, c = e & 63;
            sMean[r * LDW + c] += sS[r * LDW + c] * (1.0f / NH);
        }

        {   // O = P @ V
            float o[4][4] = {};
#pragma unroll 8
            for (int j = 0; j < WIN; j++) {
                float w0[4], v0[4];
#pragma unroll
                for (int i = 0; i < 4; i++)  w0[i]  = sS[(ty * 4 + i) * LDW + j];
#pragma unroll
                for (int jj = 0; jj < 4; jj++) v0[jj] = sV[j * LDW + tx * 4 + jj];
#pragma unroll
                for (int i = 0; i < 4; i++)
#pragma unroll
                    for (int jj = 0; jj < 4; jj++)
                        o[i][jj] = fmaf(w0[i], v0[jj], o[i][jj]);
            }
#pragma unroll
            for (int i = 0; i < 4; i++) {
                float* op = attended + (rowbase + ty * 4 + i) * HID + h * HD + tx * 4;
                *(float4*)op = make_float4(o[i][0], o[i][1], o[i][2], o[i][3]);
            }
        }
        __syncthreads();
    }

    // write partial head-mean for this group
    float* pm = pmean + (((size_t)b * NWIN + n) * NGRP + grp) * (WIN * WIN);
    for (int e = tid; e < WIN * WIN; e += 256)
        pm[e] = sMean[(e >> 6) * LDW + (e & 63)];
}

// combine the NGRP partial means into the block-diagonal attn map
__global__ __launch_bounds__(256)
void combine_mean(const float* __restrict__ pmean, float* __restrict__ attn)
{
    const int n = blockIdx.x, b = blockIdx.y;
    const float* pm = pmean + ((size_t)b * NWIN + n) * NGRP * (WIN * WIN);
    for (int e = threadIdx.x; e < WIN * WIN; e += 256) {
        float s = pm[e];
#pragma unroll
        for (int g = 1; g < NGRP; g++) s += pm[(size_t)g * WIN * WIN + e];
        const int r = e >> 6, c = e & 63;
        attn[(size_t)b * SEQ * SEQ + (size_t)(n * WIN + r) * SEQ + (size_t)n * WIN + c] = s;
    }
}

// ---------------- launch ----------------------------------------------------
extern "C" void kernel_launch(void* const* d_in, const int* in_sizes, int n_in,
                              void* d_out, int out_size)
{
    (void)in_sizes; (void)n_in; (void)out_size;
    const float* query = (const float*)d_in[0];
    const float* key_i = (const float*)d_in[1];
    const float* value = (const float*)d_in[2];
    const float* Wq = (const float*)d_in[3];
    const float* bq = (const float*)d_in[4];
    const float* Wk = (const float*)d_in[5];
    const float* bk = (const float*)d_in[6];
    const float* Wv = (const float*)d_in[7];
    const float* bv = (const float*)d_in[8];
    const float* Wo = (const float*)d_in[9];
    const float* bo = (const float*)d_in[10];

    float* out  = (float*)d_out;                              // [B,S,HID]
    float* attn = out + (size_t)BB * SEQ * HID;               // [B,S,S]

    float *qb, *kb, *vb, *ab, *pm;
    __nv_bfloat16 *ah, *al, *wh, *wl;
    cudaGetSymbolAddress((void**)&qb, g_q);
    cudaGetSymbolAddress((void**)&kb, g_k);
    cudaGetSymbolAddress((void**)&vb, g_v);
    cudaGetSymbolAddress((void**)&ab, g_att);
    cudaGetSymbolAddress((void**)&pm, g_pmean);
    cudaGetSymbolAddress((void**)&ah, g_ah);
    cudaGetSymbolAddress((void**)&al, g_al);
    cudaGetSymbolAddress((void**)&wh, g_wh);
    cudaGetSymbolAddress((void**)&wl, g_wl);

    const int nAct4 = MROWS * HID / 4;     // activation float4 count
    const int nW4   = HID * HID / 4;       // weight float4 count
    const int gAct  = nAct4 / 256;         // 8192 blocks
    const int gW    = nW4 / 256;           // 1024 blocks

    const dim3 gemmGrid(HID / GBN, MROWS / GBM);   // (8, 64)
    const int smemGemm = 8 * STG_W * 4;            // 81,920 B
    cudaFuncSetAttribute(gemm_bf16split, cudaFuncAttributeMaxDynamicSharedMemorySize, smemGemm);

    // Q projection
    conv_hilo<<<gAct, 256>>>((const float4*)query, ah, al, nAct4);
    conv_hilo<<<gW,   256>>>((const float4*)Wq,    wh, wl, nW4);
    gemm_bf16split<<<gemmGrid, 256, smemGemm>>>(ah, al, wh, wl, bq, qb, MROWS, HID, HID);
    // K projection
    conv_hilo<<<gAct, 256>>>((const float4*)key_i, ah, al, nAct4);
    conv_hilo<<<gW,   256>>>((const float4*)Wk,    wh, wl, nW4);
    gemm_bf16split<<<gemmGrid, 256, smemGemm>>>(ah, al, wh, wl, bk, kb, MROWS, HID, HID);
    // V projection
    conv_hilo<<<gAct, 256>>>((const float4*)value, ah, al, nAct4);
    conv_hilo<<<gW,   256>>>((const float4*)Wv,    wh, wl, nW4);
    gemm_bf16split<<<gemmGrid, 256, smemGemm>>>(ah, al, wh, wl, bv, vb, MROWS, HID, HID);

    // zero the attention map, then fill block-diagonal blocks
    cudaMemsetAsync(attn, 0, (size_t)BB * SEQ * SEQ * sizeof(float), 0);

    const int smemAttn = 5 * WIN * LDW * (int)sizeof(float);  // 83,200 B
    cudaFuncSetAttribute(attn_windows_g, cudaFuncAttributeMaxDynamicSharedMemorySize, smemAttn);
    attn_windows_g<<<dim3(NWIN, BB, NGRP), 256, smemAttn>>>(qb, kb, vb, ab, pm);
    combine_mean<<<dim3(NWIN, BB), 256>>>(pm, attn);

    // output projection
    conv_hilo<<<gAct, 256>>>((const float4*)ab, ah, al, nAct4);
    conv_hilo<<<gW,   256>>>((const float4*)Wo, wh, wl, nW4);
    gemm_bf16split<<<gemmGrid, 256, smemGemm>>>(ah, al, wh, wl, bo, out, MROWS, HID, HID);
}

// round 9
// speedup vs baseline: 2.3173x; 1.1502x over previous
#include <cuda_runtime.h>
#include <cuda_bf16.h>
#include <math.h>
#include <stdint.h>

// Problem constants (shape-specialized benchmark)
#define BB      2
#define SEQ     4096
#define HID     1024
#define NH      16
#define HD      64
#define WIN     64
#define NWIN    (SEQ / WIN)          // 64
#define MROWS   (BB * SEQ)           // 8192
#define NGRP    4                    // head groups for attention
#define HPG     (NH / NGRP)          // heads per group

// ---------------- scratch (device globals; no cudaMalloc allowed) ----------
__device__ float g_q[MROWS * HID];
__device__ float g_k[MROWS * HID];
__device__ float g_v[MROWS * HID];
__device__ float g_pmean[(size_t)BB * NWIN * NGRP * WIN * WIN];   // 8 MB
__device__ __nv_bfloat16 g_ah[MROWS * HID];   // activation hi
__device__ __nv_bfloat16 g_al[MROWS * HID];   // activation lo
__device__ __nv_bfloat16 g_wh[HID * HID];     // weight hi
__device__ __nv_bfloat16 g_wl[HID * HID];     // weight lo

// ---------------- f32 -> bf16 hi/lo conversion -----------------------------
__global__ __launch_bounds__(256)
void conv_hilo(const float4* __restrict__ x, __nv_bfloat16* __restrict__ hi,
               __nv_bfloat16* __restrict__ lo, int n4)
{
    int i = blockIdx.x * blockDim.x + threadIdx.x;
    if (i >= n4) return;
    float4 v = x[i];
    float f[4] = {v.x, v.y, v.z, v.w};
    union { __nv_bfloat16 b[4]; uint2 u; } H, L;
#pragma unroll
    for (int j = 0; j < 4; j++) {
        H.b[j] = __float2bfloat16_rn(f[j]);
        L.b[j] = __float2bfloat16_rn(f[j] - __bfloat162float(H.b[j]));
    }
    *reinterpret_cast<uint2*>(hi + (size_t)i * 4) = H.u;
    *reinterpret_cast<uint2*>(lo + (size_t)i * 4) = L.u;
}

// ---------------- Tensor-core GEMM: C = A * B^T + bias ---------------------
// A[M,K], B[N,K] given as bf16 hi/lo pairs. Split product:
//   C ≈ Ah*Bh + Ah*Bl + Al*Bh  (fp32 accumulate)
// CTA tile 128x128x32, 8 warps of 64x32, mma.m16n8k16, cp.async 2-stage,
// 2 CTAs/SM for latency hiding.

#define GBM 128
#define GBN 128
#define GBK 32
#define LDSW 20                        // smem words per row (16 data + 4 pad)
#define STG_W (128 * LDSW)             // words per array per stage (2560)

#define CP16(dst_u32, src_ptr) \
    asm volatile("cp.async.cg.shared.global [%0], [%1], 16;\n" :: "r"(dst_u32), "l"(src_ptr))
#define CP_COMMIT() asm volatile("cp.async.commit_group;\n" ::)
#define CP_WAIT(N)  asm volatile("cp.async.wait_group %0;\n" :: "n"(N))

#define LDSM4(R, ADDR) \
    asm volatile("ldmatrix.sync.aligned.m8n8.x4.shared.b16 {%0,%1,%2,%3}, [%4];" \
                 : "=r"((R)[0]), "=r"((R)[1]), "=r"((R)[2]), "=r"((R)[3]) : "r"(ADDR))

#define MMA16816(C, A, B0, B1) \
    asm volatile("mma.sync.aligned.m16n8k16.row.col.f32.bf16.bf16.f32 " \
                 "{%0,%1,%2,%3},{%4,%5,%6,%7},{%8,%9},{%0,%1,%2,%3};" \
                 : "+f"((C)[0]), "+f"((C)[1]), "+f"((C)[2]), "+f"((C)[3]) \
                 : "r"((A)[0]), "r"((A)[1]), "r"((A)[2]), "r"((A)[3]), "r"(B0), "r"(B1))

__global__ __launch_bounds__(256, 2)
void gemm_bf16split(const __nv_bfloat16* __restrict__ Ah, const __nv_bfloat16* __restrict__ Al,
                    const __nv_bfloat16* __restrict__ Bh, const __nv_bfloat16* __restrict__ Bl,
                    const float* __restrict__ bias, float* __restrict__ C,
                    int M, int N, int K)
{
    extern __shared__ unsigned int smem[];
    // layout (words): Ah[2][STG_W], Al[2][STG_W], Bh[2][STG_W], Bl[2][STG_W]
    const unsigned int sbase = (unsigned int)__cvta_generic_to_shared(smem);

    const int tid  = threadIdx.x;
    const int lane = tid & 31;
    const int warp = tid >> 5;
    const int wm   = warp & 1;          // 0..1 -> 64-row slab
    const int wn   = warp >> 1;         // 0..3 -> 32-col slab
    const int rowBase = blockIdx.y * GBM;
    const int colBase = blockIdx.x * GBN;
    const int NK = K / GBK;

    // ldmatrix per-lane offsets (bytes within one stage of one array)
    const int aRow = wm * 64 + ((lane >> 3) & 1) * 8 + (lane & 7);
    const unsigned int aOff = (unsigned int)(aRow * LDSW + (lane >> 4) * 4) * 4;
    const int bRow = wn * 32 + (lane >> 4) * 8 + (lane & 7);
    const unsigned int bOff = (unsigned int)(bRow * LDSW + ((lane >> 3) & 1) * 4) * 4;

    float acc[4][4][4];
#pragma unroll
    for (int i = 0; i < 4; i++)
#pragma unroll
        for (int j = 0; j < 4; j++)
#pragma unroll
            for (int r = 0; r < 4; r++) acc[i][j][r] = 0.0f;

    // ---- stage loader: 8 cp.async(16B) per thread ----
    auto load_stage = [&](int stage, int k0) {
#pragma unroll
        for (int it = 0; it < 2; it++) {
            const int cid = tid + it * 256;
            const int r = cid >> 2, c = cid & 3;
            const unsigned int soff = (unsigned int)(stage * STG_W + r * LDSW + c * 4) * 4;
            const size_t ga = (size_t)(rowBase + r) * K + k0 + c * 8;
            const size_t gb = (size_t)(colBase + r) * K + k0 + c * 8;
            CP16(sbase + 0 * STG_W * 8 + soff, Ah + ga);
            CP16(sbase + 2 * STG_W * 4 + soff, Al + ga);
            CP16(sbase + 4 * STG_W * 4 + soff, Bh + gb);
            CP16(sbase + 6 * STG_W * 4 + soff, Bl + gb);
        }
    };

    load_stage(0, 0);
    CP_COMMIT();

    for (int ks = 0; ks < NK; ks++) {
        if (ks + 1 < NK) {
            load_stage((ks + 1) & 1, (ks + 1) * GBK);
            CP_COMMIT();
            CP_WAIT(1);
        } else {
            CP_WAIT(0);
        }
        __syncthreads();

        const unsigned int st = (unsigned int)((ks & 1) * STG_W) * 4;
        const unsigned int baseAh = sbase + st;
        const unsigned int baseAl = sbase + 2 * STG_W * 4 + st;
        const unsigned int baseBh = sbase + 4 * STG_W * 4 + st;
        const unsigned int baseBl = sbase + 6 * STG_W * 4 + st;

#pragma unroll
        for (int half = 0; half < 2; half++) {
            const unsigned int kofs = (unsigned int)(half * 8) * 4;   // bytes
            // B fragments for the whole 32-col slab (16 regs live)
            unsigned int bh[4][2], bl[4][2];
#pragma unroll
            for (int p = 0; p < 2; p++) {
                const unsigned int po = (unsigned int)(p * 16 * LDSW) * 4;
                unsigned int t[4];
                LDSM4(t, baseBh + bOff + po + kofs);
                bh[2 * p][0] = t[0]; bh[2 * p][1] = t[1];
                bh[2 * p + 1][0] = t[2]; bh[2 * p + 1][1] = t[3];
                LDSM4(t, baseBl + bOff + po + kofs);
                bl[2 * p][0] = t[0]; bl[2 * p][1] = t[1];
                bl[2 * p + 1][0] = t[2]; bl[2 * p + 1][1] = t[3];
            }
            // stream A fragments one mi at a time (8 regs live) to fit 2 CTAs/SM
#pragma unroll
            for (int mi = 0; mi < 4; mi++) {
                unsigned int ah[4], al[4];
                const unsigned int mo = (unsigned int)(mi * 16 * LDSW) * 4;
                LDSM4(ah, baseAh + aOff + mo + kofs);
                LDSM4(al, baseAl + aOff + mo + kofs);
#pragma unroll
                for (int ni = 0; ni < 4; ni++) {
                    MMA16816(acc[mi][ni], ah, bh[ni][0], bh[ni][1]);
                    MMA16816(acc[mi][ni], ah, bl[ni][0], bl[ni][1]);
                    MMA16816(acc[mi][ni], al, bh[ni][0], bh[ni][1]);
                }
            }
        }
        __syncthreads();
    }

    // ---- epilogue: + bias, float2 stores ----
    const int g  = lane >> 2;
    const int kp = lane & 3;
#pragma unroll
    for (int mi = 0; mi < 4; mi++) {
#pragma unroll
        for (int ni = 0; ni < 4; ni++) {
            const int col  = colBase + wn * 32 + ni * 8 + kp * 2;
            const int row0 = rowBase + wm * 64 + mi * 16 + g;
            const float2 bv = *reinterpret_cast<const float2*>(bias + col);
            float2 v0 = make_float2(acc[mi][ni][0] + bv.x, acc[mi][ni][1] + bv.y);
            float2 v1 = make_float2(acc[mi][ni][2] + bv.x, acc[mi][ni][3] + bv.y);
            *reinterpret_cast<float2*>(C + (size_t)row0 * N + col)       = v0;
            *reinterpret_cast<float2*>(C + (size_t)(row0 + 8) * N + col) = v1;
        }
    }
}

// ---------------- Windowed attention (head-group split) --------------------
// Writes attended directly as bf16 hi/lo (feeds the Wo GEMM, no conv pass).
#define LDW 65   // smem row stride (64 + 1 pad)

__global__ __launch_bounds__(256)
void attn_windows_g(const float* __restrict__ Q, const float* __restrict__ Kp,
                    const float* __restrict__ V,
                    __nv_bfloat16* __restrict__ attHi, __nv_bfloat16* __restrict__ attLo,
                    float* __restrict__ pmean)
{
    extern __shared__ float sm[];
    float* sQ    = sm;
    float* sK    = sQ + WIN * LDW;
    float* sV    = sK + WIN * LDW;
    float* sS    = sV + WIN * LDW;
    float* sMean = sS + WIN * LDW;

    const int n   = blockIdx.x;
    const int b   = blockIdx.y;
    const int grp = blockIdx.z;
    const int tid = threadIdx.x;
    const int tx  = tid & 15;
    const int ty  = tid >> 4;
    const float scale = 0.125f;   // 1/sqrt(64)

    for (int e = tid; e < WIN * WIN; e += 256)
        sMean[(e >> 6) * LDW + (e & 63)] = 0.0f;
    __syncthreads();

    const size_t rowbase = (size_t)b * SEQ + (size_t)n * WIN;

    for (int h = grp * HPG; h < grp * HPG + HPG; h++) {
        for (int e = tid; e < WIN * WIN; e += 256) {
            const int r = e >> 6, c = e & 63;
            const size_t gidx = (rowbase + r) * HID + h * HD + c;
            sQ[r * LDW + c] = Q[gidx];
            sK[r * LDW + c] = Kp[gidx];
            sV[r * LDW + c] = V[gidx];
        }
        __syncthreads();

        {   // scores: 4x4 register tile per thread
            float acc[4][4] = {};
#pragma unroll 8
            for (int d = 0; d < HD; d++) {
                float a0[4], b0[4];
#pragma unroll
                for (int i = 0; i < 4; i++) a0[i] = sQ[(ty * 4 + i) * LDW + d];
#pragma unroll
                for (int j = 0; j < 4; j++) b0[j] = sK[(tx * 4 + j) * LDW + d];
#pragma unroll
                for (int i = 0; i < 4; i++)
#pragma unroll
                    for (int j = 0; j < 4; j++)
                        acc[i][j] = fmaf(a0[i], b0[j], acc[i][j]);
            }
#pragma unroll
            for (int i = 0; i < 4; i++)
#pragma unroll
                for (int j = 0; j < 4; j++)
                    sS[(ty * 4 + i) * LDW + tx * 4 + j] = acc[i][j] * scale;
        }
        __syncthreads();

        // row softmax (one thread per row; deterministic)
        if (tid < WIN) {
            float* row = sS + tid * LDW;
            float m = row[0];
#pragma unroll 8
            for (int j = 1; j < WIN; j++) m = fmaxf(m, row[j]);
            float s = 0.0f;
#pragma unroll 8
            for (int j = 0; j < WIN; j++) { float e = expf(row[j] - m); row[j] = e; s += e; }
            const float inv = 1.0f / s;
#pragma unroll 8
            for (int j = 0; j < WIN; j++) row[j] *= inv;
        }
        __syncthreads();

        for (int e = tid; e < WIN * WIN; e += 256) {
            const int r = e >> 6, c = e & 63;
            sMean[r * LDW + c] += sS[r * LDW + c] * (1.0f / NH);
        }

        {   // O = P @ V
            float o[4][4] = {};
#pragma unroll 8
            for (int j = 0; j < WIN; j++) {
                float w0[4], v0[4];
#pragma unroll
                for (int i = 0; i < 4; i++)  w0[i]  = sS[(ty * 4 + i) * LDW + j];
#pragma unroll
                for (int jj = 0; jj < 4; jj++) v0[jj] = sV[j * LDW + tx * 4 + jj];
#pragma unroll
                for (int i = 0; i < 4; i++)
#pragma unroll
                    for (int jj = 0; jj < 4; jj++)
                        o[i][jj] = fmaf(w0[i], v0[jj], o[i][jj]);
            }
#pragma unroll
            for (int i = 0; i < 4; i++) {
                const size_t off = (rowbase + ty * 4 + i) * HID + h * HD + tx * 4;
                union { __nv_bfloat16 b[4]; uint2 u; } H, L;
#pragma unroll
                for (int jj = 0; jj < 4; jj++) {
                    H.b[jj] = __float2bfloat16_rn(o[i][jj]);
                    L.b[jj] = __float2bfloat16_rn(o[i][jj] - __bfloat162float(H.b[jj]));
                }
                *reinterpret_cast<uint2*>(attHi + off) = H.u;
                *reinterpret_cast<uint2*>(attLo + off) = L.u;
            }
        }
        __syncthreads();
    }

    // write partial head-mean for this group
    float* pm = pmean + (((size_t)b * NWIN + n) * NGRP + grp) * (WIN * WIN);
    for (int e = tid; e < WIN * WIN; e += 256)
        pm[e] = sMean[(e >> 6) * LDW + (e & 63)];
}

// combine the NGRP partial means into the block-diagonal attn map
__global__ __launch_bounds__(256)
void combine_mean(const float* __restrict__ pmean, float* __restrict__ attn)
{
    const int n = blockIdx.x, b = blockIdx.y;
    const float* pm = pmean + ((size_t)b * NWIN + n) * NGRP * (WIN * WIN);
    for (int e = threadIdx.x; e < WIN * WIN; e += 256) {
        float s = pm[e];
#pragma unroll
        for (int g = 1; g < NGRP; g++) s += pm[(size_t)g * WIN * WIN + e];
        const int r = e >> 6, c = e & 63;
        attn[(size_t)b * SEQ * SEQ + (size_t)(n * WIN + r) * SEQ + (size_t)n * WIN + c] = s;
    }
}

// ---------------- launch ----------------------------------------------------
extern "C" void kernel_launch(void* const* d_in, const int* in_sizes, int n_in,
                              void* d_out, int out_size)
{
    (void)in_sizes; (void)n_in; (void)out_size;
    const float* query = (const float*)d_in[0];
    const float* key_i = (const float*)d_in[1];
    const float* value = (const float*)d_in[2];
    const float* Wq = (const float*)d_in[3];
    const float* bq = (const float*)d_in[4];
    const float* Wk = (const float*)d_in[5];
    const float* bk = (const float*)d_in[6];
    const float* Wv = (const float*)d_in[7];
    const float* bv = (const float*)d_in[8];
    const float* Wo = (const float*)d_in[9];
    const float* bo = (const float*)d_in[10];

    float* out  = (float*)d_out;                              // [B,S,HID]
    float* attn = out + (size_t)BB * SEQ * HID;               // [B,S,S]

    float *qb, *kb, *vb, *pm;
    __nv_bfloat16 *ah, *al, *wh, *wl;
    cudaGetSymbolAddress((void**)&qb, g_q);
    cudaGetSymbolAddress((void**)&kb, g_k);
    cudaGetSymbolAddress((void**)&vb, g_v);
    cudaGetSymbolAddress((void**)&pm, g_pmean);
    cudaGetSymbolAddress((void**)&ah, g_ah);
    cudaGetSymbolAddress((void**)&al, g_al);
    cudaGetSymbolAddress((void**)&wh, g_wh);
    cudaGetSymbolAddress((void**)&wl, g_wl);

    const int nAct4 = MROWS * HID / 4;     // activation float4 count
    const int nW4   = HID * HID / 4;       // weight float4 count
    const int gAct  = nAct4 / 256;
    const int gW    = nW4 / 256;

    const dim3 gemmGrid(HID / GBN, MROWS / GBM);   // (8, 64)
    const int smemGemm = 8 * STG_W * 4;            // 81,920 B
    cudaFuncSetAttribute(gemm_bf16split, cudaFuncAttributeMaxDynamicSharedMemorySize, smemGemm);

    // Q projection
    conv_hilo<<<gAct, 256>>>((const float4*)query, ah, al, nAct4);
    conv_hilo<<<gW,   256>>>((const float4*)Wq,    wh, wl, nW4);
    gemm_bf16split<<<gemmGrid, 256, smemGemm>>>(ah, al, wh, wl, bq, qb, MROWS, HID, HID);
    // K projection
    conv_hilo<<<gAct, 256>>>((const float4*)key_i, ah, al, nAct4);
    conv_hilo<<<gW,   256>>>((const float4*)Wk,    wh, wl, nW4);
    gemm_bf16split<<<gemmGrid, 256, smemGemm>>>(ah, al, wh, wl, bk, kb, MROWS, HID, HID);
    // V projection
    conv_hilo<<<gAct, 256>>>((const float4*)value, ah, al, nAct4);
    conv_hilo<<<gW,   256>>>((const float4*)Wv,    wh, wl, nW4);
    gemm_bf16split<<<gemmGrid, 256, smemGemm>>>(ah, al, wh, wl, bv, vb, MROWS, HID, HID);

    // zero the attention map, then fill block-diagonal blocks
    cudaMemsetAsync(attn, 0, (size_t)BB * SEQ * SEQ * sizeof(float), 0);

    // attention writes attended directly as bf16 hi/lo into g_ah/g_al
    const int smemAttn = 5 * WIN * LDW * (int)sizeof(float);  // 83,200 B
    cudaFuncSetAttribute(attn_windows_g, cudaFuncAttributeMaxDynamicSharedMemorySize, smemAttn);
    attn_windows_g<<<dim3(NWIN, BB, NGRP), 256, smemAttn>>>(qb, kb, vb, ah, al, pm);
    combine_mean<<<dim3(NWIN, BB), 256>>>(pm, attn);

    // output projection (consumes fused hi/lo attended)
    conv_hilo<<<gW, 256>>>((const float4*)Wo, wh, wl, nW4);
    gemm_bf16split<<<gemmGrid, 256, smemGemm>>>(ah, al, wh, wl, bo, out, MROWS, HID, HID);
}

// round 13
// speedup vs baseline: 2.8710x; 1.2389x over previous
#include <cuda_runtime.h>
#include <cuda_fp16.h>
#include <math.h>
#include <stdint.h>

// Problem constants (shape-specialized benchmark)
#define BB      2
#define SEQ     4096
#define HID     1024
#define NH      16
#define HD      64
#define WIN     64
#define NWIN    (SEQ / WIN)          // 64
#define MROWS   (BB * SEQ)           // 8192
#define NGRP    4                    // head groups for attention
#define HPG     (NH / NGRP)          // heads per group

// ---------------- scratch (device globals; no cudaMalloc allowed) ----------
__device__ float g_q[MROWS * HID];
__device__ float g_k[MROWS * HID];
__device__ float g_v[MROWS * HID];
__device__ float g_pmean[(size_t)BB * NWIN * NGRP * WIN * WIN];   // 8 MB
__device__ __half g_ah[MROWS * HID];   // activation hi (fp16)
__device__ __half g_al[MROWS * HID];   // activation lo (fp16)
__device__ __half g_wh[HID * HID];     // weight hi (fp16)

// ---------------- f32 -> fp16 hi/lo conversion -----------------------------
__global__ __launch_bounds__(256)
void conv_hilo(const float4* __restrict__ x, __half* __restrict__ hi,
               __half* __restrict__ lo, int n4)
{
    int i = blockIdx.x * blockDim.x + threadIdx.x;
    if (i >= n4) return;
    float4 v = x[i];
    float f[4] = {v.x, v.y, v.z, v.w};
    union { __half b[4]; uint2 u; } H, L;
#pragma unroll
    for (int j = 0; j < 4; j++) {
        H.b[j] = __float2half_rn(f[j]);
        L.b[j] = __float2half_rn(f[j] - __half2float(H.b[j]));
    }
    *reinterpret_cast<uint2*>(hi + (size_t)i * 4) = H.u;
    *reinterpret_cast<uint2*>(lo + (size_t)i * 4) = L.u;
}

// weights: hi only (B-side lo term is dropped)
__global__ __launch_bounds__(256)
void conv_hi(const float4* __restrict__ x, __half* __restrict__ hi, int n4)
{
    int i = blockIdx.x * blockDim.x + threadIdx.x;
    if (i >= n4) return;
    float4 v = x[i];
    float f[4] = {v.x, v.y, v.z, v.w};
    union { __half b[4]; uint2 u; } H;
#pragma unroll
    for (int j = 0; j < 4; j++) H.b[j] = __float2half_rn(f[j]);
    *reinterpret_cast<uint2*>(hi + (size_t)i * 4) = H.u;
}

// ---------------- Tensor-core GEMM: C = A * B^T + bias ---------------------
// A[M,K] fp16 hi/lo, B[N,K] fp16 hi. C ≈ Ah*Bh + Al*Bh (fp32 accumulate).
// CTA tile 128x128x32, 8 warps of 64x32, mma.m16n8k16.f16, cp.async 3-stage,
// 2 CTAs/SM.

#define GBM 128
#define GBN 128
#define GBK 32
#define LDSW 20                        // smem words per row (16 data + 4 pad)
#define STG_W (128 * LDSW)             // words per array per stage (2560)
#define NARR 3                         // Ah, Al, Bh
#define NSTAGE 3
#define GSMEM (NSTAGE * NARR * STG_W * 4)   // 92,160 B

#define CP16(dst_u32, src_ptr) \
    asm volatile("cp.async.cg.shared.global [%0], [%1], 16;\n" :: "r"(dst_u32), "l"(src_ptr))
#define CP_COMMIT() asm volatile("cp.async.commit_group;\n" ::)
#define CP_WAIT(N)  asm volatile("cp.async.wait_group %0;\n" :: "n"(N))

#define LDSM4(R, ADDR) \
    asm volatile("ldmatrix.sync.aligned.m8n8.x4.shared.b16 {%0,%1,%2,%3}, [%4];" \
                 : "=r"((R)[0]), "=r"((R)[1]), "=r"((R)[2]), "=r"((R)[3]) : "r"(ADDR))

#define MMA16816(C, A, B0, B1) \
    asm volatile("mma.sync.aligned.m16n8k16.row.col.f32.f16.f16.f32 " \
                 "{%0,%1,%2,%3},{%4,%5,%6,%7},{%8,%9},{%0,%1,%2,%3};" \
                 : "+f"((C)[0]), "+f"((C)[1]), "+f"((C)[2]), "+f"((C)[3]) \
                 : "r"((A)[0]), "r"((A)[1]), "r"((A)[2]), "r"((A)[3]), "r"(B0), "r"(B1))

__global__ __launch_bounds__(256, 2)
void gemm_f16split(const __half* __restrict__ Ah, const __half* __restrict__ Al,
                   const __half* __restrict__ Bh,
                   const float* __restrict__ bias, float* __restrict__ C,
                   int M, int N, int K)
{
    extern __shared__ unsigned int smem[];
    const unsigned int sbase = (unsigned int)__cvta_generic_to_shared(smem);

    const int tid  = threadIdx.x;
    const int lane = tid & 31;
    const int warp = tid >> 5;
    const int wm   = warp & 1;          // 0..1 -> 64-row slab
    const int wn   = warp >> 1;         // 0..3 -> 32-col slab
    const int rowBase = blockIdx.y * GBM;
    const int colBase = blockIdx.x * GBN;
    const int NK = K / GBK;

    // ldmatrix per-lane offsets (bytes within one stage of one array)
    const int aRow = wm * 64 + ((lane >> 3) & 1) * 8 + (lane & 7);
    const unsigned int aOff = (unsigned int)(aRow * LDSW + (lane >> 4) * 4) * 4;
    const int bRow = wn * 32 + (lane >> 4) * 8 + (lane & 7);
    const unsigned int bOff = (unsigned int)(bRow * LDSW + ((lane >> 3) & 1) * 4) * 4;

    float acc[4][4][4];
#pragma unroll
    for (int i = 0; i < 4; i++)
#pragma unroll
        for (int j = 0; j < 4; j++)
#pragma unroll
            for (int r = 0; r < 4; r++) acc[i][j][r] = 0.0f;

    // ---- stage loader: 6 cp.async(16B) per thread (Ah, Al, Bh tiles) ----
    auto load_stage = [&](int stage, int k0) {
        const unsigned int sb = sbase + (unsigned int)(stage * NARR * STG_W) * 4;
#pragma unroll
        for (int it = 0; it < 2; it++) {
            const int cid = tid + it * 256;          // 0..511 within array
            const int r = cid >> 2, c = cid & 3;
            const unsigned int soff = (unsigned int)(r * LDSW + c * 4) * 4;
            const size_t ga = (size_t)(rowBase + r) * K + k0 + c * 8;
            const size_t gb = (size_t)(colBase + r) * K + k0 + c * 8;
            CP16(sb + 0 * STG_W * 4 + soff, Ah + ga);
            CP16(sb + 1 * STG_W * 4 + soff, Al + ga);
            CP16(sb + 2 * STG_W * 4 + soff, Bh + gb);
        }
    };

    load_stage(0, 0);
    CP_COMMIT();
    load_stage(1, GBK);
    CP_COMMIT();

    for (int ks = 0; ks < NK; ks++) {
        if (ks == NK - 1) { CP_WAIT(0); } else { CP_WAIT(1); }
        __syncthreads();
        // prefetch stage ks+2 (its buffer was consumed at iteration ks-1)
        if (ks + 2 < NK) {
            load_stage((ks + 2) % NSTAGE, (ks + 2) * GBK);
            CP_COMMIT();
        }

        const unsigned int sb = sbase + (unsigned int)((ks % NSTAGE) * NARR * STG_W) * 4;
        const unsigned int baseAh = sb;
        const unsigned int baseAl = sb + 1 * STG_W * 4;
        const unsigned int baseBh = sb + 2 * STG_W * 4;

#pragma unroll
        for (int half = 0; half < 2; half++) {
            const unsigned int kofs = (unsigned int)(half * 8) * 4;   // bytes
            // B fragments for the whole 32-col slab (8 regs live)
            unsigned int bh[4][2];
#pragma unroll
            for (int p = 0; p < 2; p++) {
                const unsigned int po = (unsigned int)(p * 16 * LDSW) * 4;
                unsigned int t[4];
                LDSM4(t, baseBh + bOff + po + kofs);
                bh[2 * p][0] = t[0]; bh[2 * p][1] = t[1];
                bh[2 * p + 1][0] = t[2]; bh[2 * p + 1][1] = t[3];
            }
            // stream A fragments one mi at a time
#pragma unroll
            for (int mi = 0; mi < 4; mi++) {
                unsigned int ah[4], al[4];
                const unsigned int mo = (unsigned int)(mi * 16 * LDSW) * 4;
                LDSM4(ah, baseAh + aOff + mo + kofs);
                LDSM4(al, baseAl + aOff + mo + kofs);
#pragma unroll
                for (int ni = 0; ni < 4; ni++) {
                    MMA16816(acc[mi][ni], ah, bh[ni][0], bh[ni][1]);
                    MMA16816(acc[mi][ni], al, bh[ni][0], bh[ni][1]);
                }
            }
        }
        __syncthreads();   // all warps done with this buffer before its reuse
    }

    // ---- epilogue: + bias, float2 stores ----
    const int g  = lane >> 2;
    const int kp = lane & 3;
#pragma unroll
    for (int mi = 0; mi < 4; mi++) {
#pragma unroll
        for (int ni = 0; ni < 4; ni++) {
            const int col  = colBase + wn * 32 + ni * 8 + kp * 2;
            const int row0 = rowBase + wm * 64 + mi * 16 + g;
            const float2 bv = *reinterpret_cast<const float2*>(bias + col);
            float2 v0 = make_float2(acc[mi][ni][0] + bv.x, acc[mi][ni][1] + bv.y);
            float2 v1 = make_float2(acc[mi][ni][2] + bv.x, acc[mi][ni][3] + bv.y);
            *reinterpret_cast<float2*>(C + (size_t)row0 * N + col)       = v0;
            *reinterpret_cast<float2*>(C + (size_t)(row0 + 8) * N + col) = v1;
        }
    }
}

// ---------------- Windowed attention (head-group split) --------------------
// Writes attended directly as fp16 hi/lo (feeds the Wo GEMM, no conv pass).
#define LDW 65   // smem row stride (64 + 1 pad)

__global__ __launch_bounds__(256)
void attn_windows_g(const float* __restrict__ Q, const float* __restrict__ Kp,
                    const float* __restrict__ V,
                    __half* __restrict__ attHi, __half* __restrict__ attLo,
                    float* __restrict__ pmean)
{
    extern __shared__ float sm[];
    float* sQ    = sm;
    float* sK    = sQ + WIN * LDW;
    float* sV    = sK + WIN * LDW;
    float* sS    = sV + WIN * LDW;
    float* sMean = sS + WIN * LDW;

    const int n   = blockIdx.x;
    const int b   = blockIdx.y;
    const int grp = blockIdx.z;
    const int tid = threadIdx.x;
    const int tx  = tid & 15;
    const int ty  = tid >> 4;
    const float scale = 0.125f;   // 1/sqrt(64)

    for (int e = tid; e < WIN * WIN; e += 256)
        sMean[(e >> 6) * LDW + (e & 63)] = 0.0f;
    __syncthreads();

    const size_t rowbase = (size_t)b * SEQ + (size_t)n * WIN;

    for (int h = grp * HPG; h < grp * HPG + HPG; h++) {
        for (int e = tid; e < WIN * WIN; e += 256) {
            const int r = e >> 6, c = e & 63;
            const size_t gidx = (rowbase + r) * HID + h * HD + c;
            sQ[r * LDW + c] = Q[gidx];
            sK[r * LDW + c] = Kp[gidx];
            sV[r * LDW + c] = V[gidx];
        }
        __syncthreads();

        {   // scores: 4x4 register tile per thread
            float acc[4][4] = {};
#pragma unroll 8
            for (int d = 0; d < HD; d++) {
                float a0[4], b0[4];
#pragma unroll
                for (int i = 0; i < 4; i++) a0[i] = sQ[(ty * 4 + i) * LDW + d];
#pragma unroll
                for (int j = 0; j < 4; j++) b0[j] = sK[(tx * 4 + j) * LDW + d];
#pragma unroll
                for (int i = 0; i < 4; i++)
#pragma unroll
                    for (int j = 0; j < 4; j++)
                        acc[i][j] = fmaf(a0[i], b0[j], acc[i][j]);
            }
#pragma unroll
            for (int i = 0; i < 4; i++)
#pragma unroll
                for (int j = 0; j < 4; j++)
                    sS[(ty * 4 + i) * LDW + tx * 4 + j] = acc[i][j] * scale;
        }
        __syncthreads();

        // row softmax (one thread per row; deterministic)
        if (tid < WIN) {
            float* row = sS + tid * LDW;
            float m = row[0];
#pragma unroll 8
            for (int j = 1; j < WIN; j++) m = fmaxf(m, row[j]);
            float s = 0.0f;
#pragma unroll 8
            for (int j = 0; j < WIN; j++) { float e = expf(row[j] - m); row[j] = e; s += e; }
            const float inv = 1.0f / s;
#pragma unroll 8
            for (int j = 0; j < WIN; j++) row[j] *= inv;
        }
        __syncthreads();

        for (int e = tid; e < WIN * WIN; e += 256) {
            const int r = e >> 6, c = e & 63;
            sMean[r * LDW + c] += sS[r * LDW + c] * (1.0f / NH);
        }

        {   // O = P @ V
            float o[4][4] = {};
#pragma unroll 8
            for (int j = 0; j < WIN; j++) {
                float w0[4], v0[4];
#pragma unroll
                for (int i = 0; i < 4; i++)  w0[i]  = sS[(ty * 4 + i) * LDW + j];
#pragma unroll
                for (int jj = 0; jj < 4; jj++) v0[jj] = sV[j * LDW + tx * 4 + jj];
#pragma unroll
                for (int i = 0; i < 4; i++)
#pragma unroll
                    for (int jj = 0; jj < 4; jj++)
                        o[i][jj] = fmaf(w0[i], v0[jj], o[i][jj]);
            }
#pragma unroll
            for (int i = 0; i < 4; i++) {
                const size_t off = (rowbase + ty * 4 + i) * HID + h * HD + tx * 4;
                union { __half b[4]; uint2 u; } H, L;
#pragma unroll
                for (int jj = 0; jj < 4; jj++) {
                    H.b[jj] = __float2half_rn(o[i][jj]);
                    L.b[jj] = __float2half_rn(o[i][jj] - __half2float(H.b[jj]));
                }
                *reinterpret_cast<uint2*>(attHi + off) = H.u;
                *reinterpret_cast<uint2*>(attLo + off) = L.u;
            }
        }
        __syncthreads();
    }

    // write partial head-mean for this group
    float* pm = pmean + (((size_t)b * NWIN + n) * NGRP + grp) * (WIN * WIN);
    for (int e = tid; e < WIN * WIN; e += 256)
        pm[e] = sMean[(e >> 6) * LDW + (e & 63)];
}

// combine the NGRP partial means into the block-diagonal attn map
__global__ __launch_bounds__(256)
void combine_mean(const float* __restrict__ pmean, float* __restrict__ attn)
{
    const int n = blockIdx.x, b = blockIdx.y;
    const float* pm = pmean + ((size_t)b * NWIN + n) * NGRP * (WIN * WIN);
    for (int e = threadIdx.x; e < WIN * WIN; e += 256) {
        float s = pm[e];
#pragma unroll
        for (int g = 1; g < NGRP; g++) s += pm[(size_t)g * WIN * WIN + e];
        const int r = e >> 6, c = e & 63;
        attn[(size_t)b * SEQ * SEQ + (size_t)(n * WIN + r) * SEQ + (size_t)n * WIN + c] = s;
    }
}

// ---------------- launch ----------------------------------------------------
extern "C" void kernel_launch(void* const* d_in, const int* in_sizes, int n_in,
                              void* d_out, int out_size)
{
    (void)in_sizes; (void)n_in; (void)out_size;
    const float* query = (const float*)d_in[0];
    const float* key_i = (const float*)d_in[1];
    const float* value = (const float*)d_in[2];
    const float* Wq = (const float*)d_in[3];
    const float* bq = (const float*)d_in[4];
    const float* Wk = (const float*)d_in[5];
    const float* bk = (const float*)d_in[6];
    const float* Wv = (const float*)d_in[7];
    const float* bv = (const float*)d_in[8];
    const float* Wo = (const float*)d_in[9];
    const float* bo = (const float*)d_in[10];

    float* out  = (float*)d_out;                              // [B,S,HID]
    float* attn = out + (size_t)BB * SEQ * HID;               // [B,S,S]

    float *qb, *kb, *vb, *pm;
    __half *ah, *al, *wh;
    cudaGetSymbolAddress((void**)&qb, g_q);
    cudaGetSymbolAddress((void**)&kb, g_k);
    cudaGetSymbolAddress((void**)&vb, g_v);
    cudaGetSymbolAddress((void**)&pm, g_pmean);
    cudaGetSymbolAddress((void**)&ah, g_ah);
    cudaGetSymbolAddress((void**)&al, g_al);
    cudaGetSymbolAddress((void**)&wh, g_wh);

    const int nAct4 = MROWS * HID / 4;     // activation float4 count
    const int nW4   = HID * HID / 4;       // weight float4 count
    const int gAct  = nAct4 / 256;
    const int gW    = nW4 / 256;

    const dim3 gemmGrid(HID / GBN, MROWS / GBM);   // (8, 64)
    cudaFuncSetAttribute(gemm_f16split, cudaFuncAttributeMaxDynamicSharedMemorySize, GSMEM);

    // Q projection
    conv_hilo<<<gAct, 256>>>((const float4*)query, ah, al, nAct4);
    conv_hi<<<gW, 256>>>((const float4*)Wq, wh, nW4);
    gemm_f16split<<<gemmGrid, 256, GSMEM>>>(ah, al, wh, bq, qb, MROWS, HID, HID);
    // K projection
    conv_hilo<<<gAct, 256>>>((const float4*)key_i, ah, al, nAct4);
    conv_hi<<<gW, 256>>>((const float4*)Wk, wh, nW4);
    gemm_f16split<<<gemmGrid, 256, GSMEM>>>(ah, al, wh, bk, kb, MROWS, HID, HID);
    // V projection
    conv_hilo<<<gAct, 256>>>((const float4*)value, ah, al, nAct4);
    conv_hi<<<gW, 256>>>((const float4*)Wv, wh, nW4);
    gemm_f16split<<<gemmGrid, 256, GSMEM>>>(ah, al, wh, bv, vb, MROWS, HID, HID);

    // zero the attention map, then fill block-diagonal blocks
    cudaMemsetAsync(attn, 0, (size_t)BB * SEQ * SEQ * sizeof(float), 0);

    // attention writes attended directly as fp16 hi/lo into g_ah/g_al
    const int smemAttn = 5 * WIN * LDW * (int)sizeof(float);  // 83,200 B
    cudaFuncSetAttribute(attn_windows_g, cudaFuncAttributeMaxDynamicSharedMemorySize, smemAttn);
    attn_windows_g<<<dim3(NWIN, BB, NGRP), 256, smemAttn>>>(qb, kb, vb, ah, al, pm);
    combine_mean<<<dim3(NWIN, BB), 256>>>(pm, attn);

    // output projection (consumes fused hi/lo attended)
    conv_hi<<<gW, 256>>>((const float4*)Wo, wh, nW4);
    gemm_f16split<<<gemmGrid, 256, GSMEM>>>(ah, al, wh, bo, out, MROWS, HID, HID);
}

// round 14
// speedup vs baseline: 3.4087x; 1.1873x over previous
#include <cuda_runtime.h>
#include <cuda_fp16.h>
#include <math.h>
#include <stdint.h>

// Problem constants (shape-specialized benchmark)
#define BB      2
#define SEQ     4096
#define HID     1024
#define NH      16
#define HD      64
#define WIN     64
#define NWIN    (SEQ / WIN)          // 64
#define MROWS   (BB * SEQ)           // 8192
#define NGRP    4                    // head groups for attention
#define HPG     (NH / NGRP)          // heads per group

// ---------------- scratch (device globals; no cudaMalloc allowed) ----------
__device__ float g_q[MROWS * HID];
__device__ float g_k[MROWS * HID];
__device__ float g_v[MROWS * HID];
__device__ float g_pmean[(size_t)BB * NWIN * NGRP * WIN * WIN];   // 8 MB
__device__ __half g_ah[MROWS * HID];   // activation hi (fp16)
__device__ __half g_al[MROWS * HID];   // activation lo (fp16)
__device__ __half g_wh[HID * HID];     // weight hi (fp16)

// ---------------- f32 -> fp16 hi/lo conversion -----------------------------
__global__ __launch_bounds__(256)
void conv_hilo(const float4* __restrict__ x, __half* __restrict__ hi,
               __half* __restrict__ lo, int n4)
{
    int i = blockIdx.x * blockDim.x + threadIdx.x;
    if (i >= n4) return;
    float4 v = x[i];
    float f[4] = {v.x, v.y, v.z, v.w};
    union { __half b[4]; uint2 u; } H, L;
#pragma unroll
    for (int j = 0; j < 4; j++) {
        H.b[j] = __float2half_rn(f[j]);
        L.b[j] = __float2half_rn(f[j] - __half2float(H.b[j]));
    }
    *reinterpret_cast<uint2*>(hi + (size_t)i * 4) = H.u;
    *reinterpret_cast<uint2*>(lo + (size_t)i * 4) = L.u;
}

// hi-only conversion (for weights and for 1-term activations)
__global__ __launch_bounds__(256)
void conv_hi(const float4* __restrict__ x, __half* __restrict__ hi, int n4)
{
    int i = blockIdx.x * blockDim.x + threadIdx.x;
    if (i >= n4) return;
    float4 v = x[i];
    float f[4] = {v.x, v.y, v.z, v.w};
    union { __half b[4]; uint2 u; } H;
#pragma unroll
    for (int j = 0; j < 4; j++) H.b[j] = __float2half_rn(f[j]);
    *reinterpret_cast<uint2*>(hi + (size_t)i * 4) = H.u;
}

// ---------------- Tensor-core GEMM: C = A * B^T + bias ---------------------
// A[M,K] fp16 (hi, optional lo), B[N,K] fp16 hi.
//   AL2=true :  C ≈ Ah*Bh + Al*Bh   (2-term; used for Q,K projections)
//   AL2=false:  C ≈ Ah*Bh           (1-term; used for V, Wo — linear paths)
// CTA tile 128x128x32, 8 warps of 64x32, mma.m16n8k16.f16, cp.async 3-stage,
// 2 CTAs/SM.

#define GBM 128
#define GBN 128
#define GBK 32
#define LDSW 20                        // smem words per row (16 data + 4 pad)
#define STG_W (128 * LDSW)             // words per array per stage (2560)
#define NSTAGE 3

#define CP16(dst_u32, src_ptr) \
    asm volatile("cp.async.cg.shared.global [%0], [%1], 16;\n" :: "r"(dst_u32), "l"(src_ptr))
#define CP_COMMIT() asm volatile("cp.async.commit_group;\n" ::)
#define CP_WAIT(N)  asm volatile("cp.async.wait_group %0;\n" :: "n"(N))

#define LDSM4(R, ADDR) \
    asm volatile("ldmatrix.sync.aligned.m8n8.x4.shared.b16 {%0,%1,%2,%3}, [%4];" \
                 : "=r"((R)[0]), "=r"((R)[1]), "=r"((R)[2]), "=r"((R)[3]) : "r"(ADDR))

#define MMA16816(C, A, B0, B1) \
    asm volatile("mma.sync.aligned.m16n8k16.row.col.f32.f16.f16.f32 " \
                 "{%0,%1,%2,%3},{%4,%5,%6,%7},{%8,%9},{%0,%1,%2,%3};" \
                 : "+f"((C)[0]), "+f"((C)[1]), "+f"((C)[2]), "+f"((C)[3]) \
                 : "r"((A)[0]), "r"((A)[1]), "r"((A)[2]), "r"((A)[3]), "r"(B0), "r"(B1))

template<bool AL2>
__global__ __launch_bounds__(256, 2)
void gemm_f16t(const __half* __restrict__ Ah, const __half* __restrict__ Al,
               const __half* __restrict__ Bh,
               const float* __restrict__ bias, float* __restrict__ C,
               int M, int N, int K)
{
    constexpr int NARR = AL2 ? 3 : 2;   // arrays per stage: Ah, Bh[, Al]
    extern __shared__ unsigned int smem[];
    const unsigned int sbase = (unsigned int)__cvta_generic_to_shared(smem);

    const int tid  = threadIdx.x;
    const int lane = tid & 31;
    const int warp = tid >> 5;
    const int wm   = warp & 1;          // 0..1 -> 64-row slab
    const int wn   = warp >> 1;         // 0..3 -> 32-col slab
    const int rowBase = blockIdx.y * GBM;
    const int colBase = blockIdx.x * GBN;
    const int NK = K / GBK;

    // ldmatrix per-lane offsets (bytes within one stage of one array)
    const int aRow = wm * 64 + ((lane >> 3) & 1) * 8 + (lane & 7);
    const unsigned int aOff = (unsigned int)(aRow * LDSW + (lane >> 4) * 4) * 4;
    const int bRow = wn * 32 + (lane >> 4) * 8 + (lane & 7);
    const unsigned int bOff = (unsigned int)(bRow * LDSW + ((lane >> 3) & 1) * 4) * 4;

    float acc[4][4][4];
#pragma unroll
    for (int i = 0; i < 4; i++)
#pragma unroll
        for (int j = 0; j < 4; j++)
#pragma unroll
            for (int r = 0; r < 4; r++) acc[i][j][r] = 0.0f;

    // ---- stage loader: layout per stage: Ah @0, Bh @STG_W, Al @2*STG_W ----
    auto load_stage = [&](int stage, int k0) {
        const unsigned int sb = sbase + (unsigned int)(stage * NARR * STG_W) * 4;
#pragma unroll
        for (int it = 0; it < 2; it++) {
            const int cid = tid + it * 256;          // 0..511 within array
            const int r = cid >> 2, c = cid & 3;
            const unsigned int soff = (unsigned int)(r * LDSW + c * 4) * 4;
            const size_t ga = (size_t)(rowBase + r) * K + k0 + c * 8;
            const size_t gb = (size_t)(colBase + r) * K + k0 + c * 8;
            CP16(sb + 0 * STG_W * 4 + soff, Ah + ga);
            CP16(sb + 1 * STG_W * 4 + soff, Bh + gb);
            if (AL2) CP16(sb + 2 * STG_W * 4 + soff, Al + ga);
        }
    };

    load_stage(0, 0);
    CP_COMMIT();
    load_stage(1, GBK);
    CP_COMMIT();

    for (int ks = 0; ks < NK; ks++) {
        if (ks == NK - 1) { CP_WAIT(0); } else { CP_WAIT(1); }
        __syncthreads();
        // prefetch stage ks+2 (its buffer was consumed at iteration ks-1)
        if (ks + 2 < NK) {
            load_stage((ks + 2) % NSTAGE, (ks + 2) * GBK);
            CP_COMMIT();
        }

        const unsigned int sb = sbase + (unsigned int)((ks % NSTAGE) * NARR * STG_W) * 4;
        const unsigned int baseAh = sb;
        const unsigned int baseBh = sb + 1 * STG_W * 4;
        const unsigned int baseAl = sb + 2 * STG_W * 4;

#pragma unroll
        for (int half = 0; half < 2; half++) {
            const unsigned int kofs = (unsigned int)(half * 8) * 4;   // bytes
            // B fragments for the whole 32-col slab (8 regs live)
            unsigned int bh[4][2];
#pragma unroll
            for (int p = 0; p < 2; p++) {
                const unsigned int po = (unsigned int)(p * 16 * LDSW) * 4;
                unsigned int t[4];
                LDSM4(t, baseBh + bOff + po + kofs);
                bh[2 * p][0] = t[0]; bh[2 * p][1] = t[1];
                bh[2 * p + 1][0] = t[2]; bh[2 * p + 1][1] = t[3];
            }
            // stream A fragments one mi at a time
#pragma unroll
            for (int mi = 0; mi < 4; mi++) {
                unsigned int ah[4], al[4];
                const unsigned int mo = (unsigned int)(mi * 16 * LDSW) * 4;
                LDSM4(ah, baseAh + aOff + mo + kofs);
                if (AL2) LDSM4(al, baseAl + aOff + mo + kofs);
#pragma unroll
                for (int ni = 0; ni < 4; ni++) {
                    MMA16816(acc[mi][ni], ah, bh[ni][0], bh[ni][1]);
                    if (AL2) MMA16816(acc[mi][ni], al, bh[ni][0], bh[ni][1]);
                }
            }
        }
        __syncthreads();   // all warps done with this buffer before its reuse
    }

    // ---- epilogue: + bias, float2 stores ----
    const int g  = lane >> 2;
    const int kp = lane & 3;
#pragma unroll
    for (int mi = 0; mi < 4; mi++) {
#pragma unroll
        for (int ni = 0; ni < 4; ni++) {
            const int col  = colBase + wn * 32 + ni * 8 + kp * 2;
            const int row0 = rowBase + wm * 64 + mi * 16 + g;
            const float2 bv = *reinterpret_cast<const float2*>(bias + col);
            float2 v0 = make_float2(acc[mi][ni][0] + bv.x, acc[mi][ni][1] + bv.y);
            float2 v1 = make_float2(acc[mi][ni][2] + bv.x, acc[mi][ni][3] + bv.y);
            *reinterpret_cast<float2*>(C + (size_t)row0 * N + col)       = v0;
            *reinterpret_cast<float2*>(C + (size_t)(row0 + 8) * N + col) = v1;
        }
    }
}

// ---------------- Windowed attention (head-group split) --------------------
// Writes attended directly as fp16 hi (feeds the 1-term Wo GEMM).
#define LDW 65   // smem row stride (64 + 1 pad)

__global__ __launch_bounds__(256)
void attn_windows_g(const float* __restrict__ Q, const float* __restrict__ Kp,
                    const float* __restrict__ V,
                    __half* __restrict__ attHi,
                    float* __restrict__ pmean)
{
    extern __shared__ float sm[];
    float* sQ    = sm;
    float* sK    = sQ + WIN * LDW;
    float* sV    = sK + WIN * LDW;
    float* sS    = sV + WIN * LDW;
    float* sMean = sS + WIN * LDW;

    const int n   = blockIdx.x;
    const int b   = blockIdx.y;
    const int grp = blockIdx.z;
    const int tid = threadIdx.x;
    const int tx  = tid & 15;
    const int ty  = tid >> 4;
    const float scale = 0.125f;   // 1/sqrt(64)

    for (int e = tid; e < WIN * WIN; e += 256)
        sMean[(e >> 6) * LDW + (e & 63)] = 0.0f;
    __syncthreads();

    const size_t rowbase = (size_t)b * SEQ + (size_t)n * WIN;

    for (int h = grp * HPG; h < grp * HPG + HPG; h++) {
        for (int e = tid; e < WIN * WIN; e += 256) {
            const int r = e >> 6, c = e & 63;
            const size_t gidx = (rowbase + r) * HID + h * HD + c;
            sQ[r * LDW + c] = Q[gidx];
            sK[r * LDW + c] = Kp[gidx];
            sV[r * LDW + c] = V[gidx];
        }
        __syncthreads();

        {   // scores: 4x4 register tile per thread
            float acc[4][4] = {};
#pragma unroll 8
            for (int d = 0; d < HD; d++) {
                float a0[4], b0[4];
#pragma unroll
                for (int i = 0; i < 4; i++) a0[i] = sQ[(ty * 4 + i) * LDW + d];
#pragma unroll
                for (int j = 0; j < 4; j++) b0[j] = sK[(tx * 4 + j) * LDW + d];
#pragma unroll
                for (int i = 0; i < 4; i++)
#pragma unroll
                    for (int j = 0; j < 4; j++)
                        acc[i][j] = fmaf(a0[i], b0[j], acc[i][j]);
            }
#pragma unroll
            for (int i = 0; i < 4; i++)
#pragma unroll
                for (int j = 0; j < 4; j++)
                    sS[(ty * 4 + i) * LDW + tx * 4 + j] = acc[i][j] * scale;
        }
        __syncthreads();

        // row softmax (one thread per row; deterministic)
        if (tid < WIN) {
            float* row = sS + tid * LDW;
            float m = row[0];
#pragma unroll 8
            for (int j = 1; j < WIN; j++) m = fmaxf(m, row[j]);
            float s = 0.0f;
#pragma unroll 8
            for (int j = 0; j < WIN; j++) { float e = expf(row[j] - m); row[j] = e; s += e; }
            const float inv = 1.0f / s;
#pragma unroll 8
            for (int j = 0; j < WIN; j++) row[j] *= inv;
        }
        __syncthreads();

        for (int e = tid; e < WIN * WIN; e += 256) {
            const int r = e >> 6, c = e & 63;
            sMean[r * LDW + c] += sS[r * LDW + c] * (1.0f / NH);
        }

        {   // O = P @ V
            float o[4][4] = {};
#pragma unroll 8
            for (int j = 0; j < WIN; j++) {
                float w0[4], v0[4];
#pragma unroll
                for (int i = 0; i < 4; i++)  w0[i]  = sS[(ty * 4 + i) * LDW + j];
#pragma unroll
                for (int jj = 0; jj < 4; jj++) v0[jj] = sV[j * LDW + tx * 4 + jj];
#pragma unroll
                for (int i = 0; i < 4; i++)
#pragma unroll
                    for (int jj = 0; jj < 4; jj++)
                        o[i][jj] = fmaf(w0[i], v0[jj], o[i][jj]);
            }
#pragma unroll
            for (int i = 0; i < 4; i++) {
                const size_t off = (rowbase + ty * 4 + i) * HID + h * HD + tx * 4;
                union { __half b[4]; uint2 u; } H;
#pragma unroll
                for (int jj = 0; jj < 4; jj++) H.b[jj] = __float2half_rn(o[i][jj]);
                *reinterpret_cast<uint2*>(attHi + off) = H.u;
            }
        }
        __syncthreads();
    }

    // write partial head-mean for this group
    float* pm = pmean + (((size_t)b * NWIN + n) * NGRP + grp) * (WIN * WIN);
    for (int e = tid; e < WIN * WIN; e += 256)
        pm[e] = sMean[(e >> 6) * LDW + (e & 63)];
}

// combine the NGRP partial means into the block-diagonal attn map
__global__ __launch_bounds__(256)
void combine_mean(const float* __restrict__ pmean, float* __restrict__ attn)
{
    const int n = blockIdx.x, b = blockIdx.y;
    const float* pm = pmean + ((size_t)b * NWIN + n) * NGRP * (WIN * WIN);
    for (int e = threadIdx.x; e < WIN * WIN; e += 256) {
        float s = pm[e];
#pragma unroll
        for (int g = 1; g < NGRP; g++) s += pm[(size_t)g * WIN * WIN + e];
        const int r = e >> 6, c = e & 63;
        attn[(size_t)b * SEQ * SEQ + (size_t)(n * WIN + r) * SEQ + (size_t)n * WIN + c] = s;
    }
}

// ---------------- launch ----------------------------------------------------
extern "C" void kernel_launch(void* const* d_in, const int* in_sizes, int n_in,
                              void* d_out, int out_size)
{
    (void)in_sizes; (void)n_in; (void)out_size;
    const float* query = (const float*)d_in[0];
    const float* key_i = (const float*)d_in[1];
    const float* value = (const float*)d_in[2];
    const float* Wq = (const float*)d_in[3];
    const float* bq = (const float*)d_in[4];
    const float* Wk = (const float*)d_in[5];
    const float* bk = (const float*)d_in[6];
    const float* Wv = (const float*)d_in[7];
    const float* bv = (const float*)d_in[8];
    const float* Wo = (const float*)d_in[9];
    const float* bo = (const float*)d_in[10];

    float* out  = (float*)d_out;                              // [B,S,HID]
    float* attn = out + (size_t)BB * SEQ * HID;               // [B,S,S]

    float *qb, *kb, *vb, *pm;
    __half *ah, *al, *wh;
    cudaGetSymbolAddress((void**)&qb, g_q);
    cudaGetSymbolAddress((void**)&kb, g_k);
    cudaGetSymbolAddress((void**)&vb, g_v);
    cudaGetSymbolAddress((void**)&pm, g_pmean);
    cudaGetSymbolAddress((void**)&ah, g_ah);
    cudaGetSymbolAddress((void**)&al, g_al);
    cudaGetSymbolAddress((void**)&wh, g_wh);

    const int nAct4 = MROWS * HID / 4;     // activation float4 count
    const int nW4   = HID * HID / 4;       // weight float4 count
    const int gAct  = nAct4 / 256;
    const int gW    = nW4 / 256;

    const dim3 gemmGrid(HID / GBN, MROWS / GBM);   // (8, 64)
    const int GS2 = NSTAGE * 3 * STG_W * 4;        // 92,160 B (2-term)
    const int GS1 = NSTAGE * 2 * STG_W * 4;        // 61,440 B (1-term)
    cudaFuncSetAttribute(gemm_f16t<true>,  cudaFuncAttributeMaxDynamicSharedMemorySize, GS2);
    cudaFuncSetAttribute(gemm_f16t<false>, cudaFuncAttributeMaxDynamicSharedMemorySize, GS1);

    // Q projection (2-term: feeds softmax)
    conv_hilo<<<gAct, 256>>>((const float4*)query, ah, al, nAct4);
    conv_hi<<<gW, 256>>>((const float4*)Wq, wh, nW4);
    gemm_f16t<true><<<gemmGrid, 256, GS2>>>(ah, al, wh, bq, qb, MROWS, HID, HID);
    // K projection (2-term: feeds softmax)
    conv_hilo<<<gAct, 256>>>((const float4*)key_i, ah, al, nAct4);
    conv_hi<<<gW, 256>>>((const float4*)Wk, wh, nW4);
    gemm_f16t<true><<<gemmGrid, 256, GS2>>>(ah, al, wh, bk, kb, MROWS, HID, HID);
    // V projection (1-term: linear path to outputs)
    conv_hi<<<gAct, 256>>>((const float4*)value, ah, nAct4);
    conv_hi<<<gW, 256>>>((const float4*)Wv, wh, nW4);
    gemm_f16t<false><<<gemmGrid, 256, GS1>>>(ah, (const __half*)nullptr, wh, bv, vb, MROWS, HID, HID);

    // zero the attention map, then fill block-diagonal blocks
    cudaMemsetAsync(attn, 0, (size_t)BB * SEQ * SEQ * sizeof(float), 0);

    // attention writes attended directly as fp16 hi into g_ah
    const int smemAttn = 5 * WIN * LDW * (int)sizeof(float);  // 83,200 B
    cudaFuncSetAttribute(attn_windows_g, cudaFuncAttributeMaxDynamicSharedMemorySize, smemAttn);
    attn_windows_g<<<dim3(NWIN, BB, NGRP), 256, smemAttn>>>(qb, kb, vb, ah, pm);
    combine_mean<<<dim3(NWIN, BB), 256>>>(pm, attn);

    // output projection (1-term: linear path)
    conv_hi<<<gW, 256>>>((const float4*)Wo, wh, nW4);
    gemm_f16t<false><<<gemmGrid, 256, GS1>>>(ah, (const __half*)nullptr, wh, bo, out, MROWS, HID, HID);
}